// round 5
// baseline (speedup 1.0000x reference)
#include <cuda_runtime.h>

#define NN   100000
#define EE   1600000
#define KIN  256
#define KOUT 128
#define NB_SCAN ((NN + 1023) / 1024)   // 98

// Scratch (allocation-free rule: __device__ globals)
__device__ float  g_featproj[NN * KOUT];   // 51.2 MB projected features
__device__ float2 g_edges[EE];             // dst-bucketed (src_bits, weight)
__device__ int    g_outcnt[NN];
__device__ int    g_incnt[NN];
__device__ int    g_scanpart[NN];
__device__ int    g_rowoff[NN + 1];
__device__ int    g_cursor[NN];
__device__ int    g_blocksum[NB_SCAN];
__device__ int    g_blockoff[NB_SCAN];

// ---------------------------------------------------------------------------
__global__ void k_init() {
    int i = blockIdx.x * blockDim.x + threadIdx.x;
    int stride = gridDim.x * blockDim.x;
    for (int j = i; j < NN; j += stride) { g_outcnt[j] = 0; g_incnt[j] = 0; }
    if (i == 0) g_rowoff[NN] = EE;
}

// ---------------------------------------------------------------------------
__global__ void k_deg(const int* __restrict__ src, const int* __restrict__ dst) {
    int i = blockIdx.x * blockDim.x + threadIdx.x;
    if (i < EE) {
        atomicAdd(&g_outcnt[src[i]], 1);
        atomicAdd(&g_incnt[dst[i]], 1);
    }
}

// ---------------------------------------------------------------------------
// Exclusive scan of in-degrees (3 kernels)
// ---------------------------------------------------------------------------
__device__ __forceinline__ int warpInclScan(int v) {
#pragma unroll
    for (int o = 1; o < 32; o <<= 1) {
        int n = __shfl_up_sync(0xFFFFFFFFu, v, o);
        if ((threadIdx.x & 31) >= o) v += n;
    }
    return v;
}

__global__ __launch_bounds__(1024) void k_scan1() {
    __shared__ int ws[32];
    int tid = threadIdx.x;
    int i = blockIdx.x * 1024 + tid;
    int lane = tid & 31, wid = tid >> 5;
    int v = (i < NN) ? g_incnt[i] : 0;
    int inc = warpInclScan(v);
    if (lane == 31) ws[wid] = inc;
    __syncthreads();
    if (wid == 0) ws[lane] = warpInclScan(ws[lane]);
    __syncthreads();
    int excl = inc - v + (wid > 0 ? ws[wid - 1] : 0);
    if (i < NN) g_scanpart[i] = excl;
    if (tid == 1023) g_blocksum[blockIdx.x] = ws[31];
}

__global__ __launch_bounds__(128) void k_scan2() {
    __shared__ int ws[4];
    int tid = threadIdx.x;
    int lane = tid & 31, wid = tid >> 5;
    int v = (tid < NB_SCAN) ? g_blocksum[tid] : 0;
    int inc = warpInclScan(v);
    if (lane == 31) ws[wid] = inc;
    __syncthreads();
    if (wid == 0) {
        int w = (lane < 4) ? ws[lane] : 0;   // full warp runs the shfl scan
        w = warpInclScan(w);
        if (lane < 4) ws[lane] = w;
    }
    __syncthreads();
    int excl = inc - v + (wid > 0 ? ws[wid - 1] : 0);
    if (tid < NB_SCAN) g_blockoff[tid] = excl;
}

__global__ void k_scan3() {
    int i = blockIdx.x * blockDim.x + threadIdx.x;
    if (i < NN) {
        int off = g_scanpart[i] + g_blockoff[i >> 10];
        g_rowoff[i] = off;
        g_cursor[i] = off;
    }
}

// ---------------------------------------------------------------------------
__global__ void k_bucket(const int* __restrict__ src, const int* __restrict__ dst,
                         const float* __restrict__ ew) {
    int e = blockIdx.x * blockDim.x + threadIdx.x;
    if (e < EE) {
        int d = dst[e];
        int pos = atomicAdd(&g_cursor[d], 1);
        g_edges[pos] = make_float2(__int_as_float(src[e]), ew[e]);
    }
}

// ---------------------------------------------------------------------------
// Kernel: FP32 SGEMM via packed fma.rn.f32x2, ZERO pack movs:
//  - A tile stored duplicated (Asd[k][2m]==Asd[k][2m+1]) -> LDS.64 gives (a,a)
//  - B pairs loaded as ulonglong2 (LDS.128) -> packed (b0,b1),(b2,b3) for free
// BM=128, BN=128(=KOUT), BK=8, 256 threads, 8 rows x 4 packed-col-pairs/thread
// ---------------------------------------------------------------------------
__global__ __launch_bounds__(256) void k_gemm(const float* __restrict__ feat,
                                              const float* __restrict__ weight,
                                              const float* __restrict__ maskr) {
    __shared__ float Asd[8][256];   // duplicated A: [k][2m..2m+1]
    __shared__ float Bs[8][128];    // [k][n]

    const int tid = threadIdx.x;
    const int blockRow = blockIdx.x * 128;

    const int arow = tid >> 1;          // 0..127
    const int acol = (tid & 1) * 4;     // 0 or 4
    const int grow = blockRow + arow;
    float scale = 0.f;
    if (grow < NN) scale = rsqrtf((float)max(g_outcnt[grow], 1));

    const int brow = tid >> 5;
    const int bcol = (tid & 31) * 4;
    const int ty = tid >> 4;
    const int tx = tid & 15;

    unsigned long long acc2[8][4];      // acc2[i][j] = cols {2j,2j+1} of row i
#pragma unroll
    for (int i = 0; i < 8; i++)
#pragma unroll
        for (int j = 0; j < 4; j++) acc2[i][j] = 0ULL;

    for (int k0 = 0; k0 < KIN; k0 += 8) {
        float4 a = make_float4(0.f, 0.f, 0.f, 0.f);
        if (grow < NN)
            a = *reinterpret_cast<const float4*>(&feat[grow * KIN + k0 + acol]);
        a.x *= scale; a.y *= scale; a.z *= scale; a.w *= scale;
        *reinterpret_cast<float2*>(&Asd[acol + 0][2 * arow]) = make_float2(a.x, a.x);
        *reinterpret_cast<float2*>(&Asd[acol + 1][2 * arow]) = make_float2(a.y, a.y);
        *reinterpret_cast<float2*>(&Asd[acol + 2][2 * arow]) = make_float2(a.z, a.z);
        *reinterpret_cast<float2*>(&Asd[acol + 3][2 * arow]) = make_float2(a.w, a.w);

        float4 w4 = *reinterpret_cast<const float4*>(&weight[(k0 + brow) * KOUT + bcol]);
        float4 m4 = *reinterpret_cast<const float4*>(&maskr [(k0 + brow) * KOUT + bcol]);
        w4.x = (m4.x > 0.5f) ? w4.x : 0.f;
        w4.y = (m4.y > 0.5f) ? w4.y : 0.f;
        w4.z = (m4.z > 0.5f) ? w4.z : 0.f;
        w4.w = (m4.w > 0.5f) ? w4.w : 0.f;
        *reinterpret_cast<float4*>(&Bs[brow][bcol]) = w4;

        __syncthreads();

#pragma unroll
        for (int k = 0; k < 8; k++) {
            unsigned long long br2[4];
            ulonglong2 b01 = *reinterpret_cast<const ulonglong2*>(&Bs[k][tx * 8]);
            ulonglong2 b23 = *reinterpret_cast<const ulonglong2*>(&Bs[k][tx * 8 + 4]);
            br2[0] = b01.x; br2[1] = b01.y; br2[2] = b23.x; br2[3] = b23.y;

            unsigned long long ar2[8];
#pragma unroll
            for (int i = 0; i < 8; i++)
                ar2[i] = *reinterpret_cast<const unsigned long long*>(
                             &Asd[k][2 * (ty * 8 + i)]);

#pragma unroll
            for (int i = 0; i < 8; i++)
#pragma unroll
                for (int j = 0; j < 4; j++)
                    asm("fma.rn.f32x2 %0, %1, %2, %0;"
                        : "+l"(acc2[i][j]) : "l"(ar2[i]), "l"(br2[j]));
        }
        __syncthreads();
    }

#pragma unroll
    for (int i = 0; i < 8; i++) {
        int r = blockRow + ty * 8 + i;
        if (r < NN) {
            *reinterpret_cast<ulonglong2*>(&g_featproj[r * KOUT + tx * 8]) =
                make_ulonglong2(acc2[i][0], acc2[i][1]);
            *reinterpret_cast<ulonglong2*>(&g_featproj[r * KOUT + tx * 8 + 4]) =
                make_ulonglong2(acc2[i][2], acc2[i][3]);
        }
    }
}

// ---------------------------------------------------------------------------
// Kernel: aggregation. One warp per dst node, atomic-free, fused finalize.
// ---------------------------------------------------------------------------
__global__ __launch_bounds__(256) void k_agg(float* __restrict__ out,
                                             const float* __restrict__ bias) {
    int node = blockIdx.x * 8 + (threadIdx.x >> 5);
    int lane = threadIdx.x & 31;
    if (node >= NN) return;

    int beg = g_rowoff[node];
    int end = g_rowoff[node + 1];

    float4 acc = make_float4(0.f, 0.f, 0.f, 0.f);
    int e = beg;
    for (; e + 1 < end; e += 2) {
        float2 e0 = g_edges[e];
        float2 e1 = g_edges[e + 1];
        int s0 = __float_as_int(e0.x);
        int s1 = __float_as_int(e1.x);
        float4 v0 = *reinterpret_cast<const float4*>(&g_featproj[s0 * KOUT + lane * 4]);
        float4 v1 = *reinterpret_cast<const float4*>(&g_featproj[s1 * KOUT + lane * 4]);
        acc.x = fmaf(e0.y, v0.x, fmaf(e1.y, v1.x, acc.x));
        acc.y = fmaf(e0.y, v0.y, fmaf(e1.y, v1.y, acc.y));
        acc.z = fmaf(e0.y, v0.z, fmaf(e1.y, v1.z, acc.z));
        acc.w = fmaf(e0.y, v0.w, fmaf(e1.y, v1.w, acc.w));
    }
    if (e < end) {
        float2 e0 = g_edges[e];
        int s0 = __float_as_int(e0.x);
        float4 v0 = *reinterpret_cast<const float4*>(&g_featproj[s0 * KOUT + lane * 4]);
        acc.x = fmaf(e0.y, v0.x, acc.x);
        acc.y = fmaf(e0.y, v0.y, acc.y);
        acc.z = fmaf(e0.y, v0.z, acc.z);
        acc.w = fmaf(e0.y, v0.w, acc.w);
    }

    float sc = rsqrtf((float)max(end - beg, 1));
    float4 b = *reinterpret_cast<const float4*>(&bias[lane * 4]);
    acc.x = fmaf(acc.x, sc, b.x);
    acc.y = fmaf(acc.y, sc, b.y);
    acc.z = fmaf(acc.z, sc, b.z);
    acc.w = fmaf(acc.w, sc, b.w);
    *reinterpret_cast<float4*>(&out[node * KOUT + lane * 4]) = acc;
}

// ---------------------------------------------------------------------------
extern "C" void kernel_launch(void* const* d_in, const int* in_sizes, int n_in,
                              void* d_out, int out_size) {
    const float* feat   = (const float*)d_in[0];
    const int*   src    = (const int*)  d_in[1];
    const int*   dst    = (const int*)  d_in[2];
    const float* ew     = (const float*)d_in[3];
    const float* weight = (const float*)d_in[4];
    const float* bias   = (const float*)d_in[5];
    const float* maskr  = (const float*)d_in[6];
    float* out = (float*)d_out;

    k_init<<<256, 256>>>();
    k_deg<<<(EE + 255) / 256, 256>>>(src, dst);
    k_scan1<<<NB_SCAN, 1024>>>();
    k_scan2<<<1, 128>>>();
    k_scan3<<<(NN + 255) / 256, 256>>>();
    k_bucket<<<(EE + 255) / 256, 256>>>(src, dst, ew);
    k_gemm<<<(NN + 127) / 128, 256>>>(feat, weight, maskr);
    k_agg<<<(NN + 7) / 8, 256>>>(out, bias);
}